// round 16
// baseline (speedup 1.0000x reference)
#include <cuda_runtime.h>
#include <cuda_fp16.h>
#include <cstdint>

// dendriticNet fused stepper, GB300 sm_103a — Round 16: B-resident persistent.
// 18 uniform groups = 9 GEMM terms x 2 col-halves. Each CTA holds its term's
// 80KB weight pack resident in smem and streams A over 16 row-tiles (128x128).
// Per-chunk L1 bytes drop 72KB -> 56KB (no B-fill, no cp.async in loop).
// out0/out1 (3-term) accumulate via red.global.add into a zeroed region
// (zeroing fused into the prep launch); out2/3/4 use direct epilogue + nudge.
// 256 thr, 8 warps 4(M)x2(N) warp-tile 32x64 (regs ~128), 2 CTAs/SM.
//
// Graph-capture safe: two kernel launches, no allocs, scratch = __device__.

#define B_ROWS   32768
#define HDIM     256
#define BM       128            // rows per tile
#define BK       32
#define NTHREADS 256
#define NBUF_A   4

#define A_BYTES   8192              // 128 x 32 halves, A-fragment order
#define B_CHUNK   10240             // 128 cols x 32 k halves, 80B/lane
#define B_FULL    20480             // 256-col chunk in the weight pack
#define B_RES     (8 * B_CHUNK)     // 81920: full K=256 for one col-half
#define NSM_OFF   (NBUF_A * A_BYTES + B_RES)     // 114688
#define SMEM_BYTES (NSM_OFF + 512)               // 115200 (nudge scratch)
#define W_PACK_BYTES (8 * B_FULL)

#define TILES_PER_CTA 16
#define GC_TOTAL  (TILES_PER_CTA * 8)            // 128 chunks per CTA
#define GRID_FUSED (18 * 16)                     // 288 CTAs = one wave

// Folded constants (DT=0.1, GLK=0.1, GB=1.0, GA=0.8, GD=1.0, GSOM=0.8)
#define ALPHA_S   0.81f
#define ALPHA_S2  0.89f
#define ALPHA_I   0.81f
#define C_B       0.10f
#define C_A       0.08f
#define C_D       0.10f
#define C_SOM     0.08f

#define PREP_THREADS  512
#define PREP_W_BLOCKS 144
#define PREP_Z_BLOCKS 1024       // zero out0/out1: 1024*512*8 float4 = 64MB

__device__ __align__(16) unsigned char g_wpack[9][W_PACK_BYTES];

// ---------------------------------------------------------------------------
// helpers
// ---------------------------------------------------------------------------
__device__ __forceinline__ uint32_t smem_u32(const void* p) {
    uint32_t a;
    asm("{ .reg .u64 t; cvta.to.shared.u64 t, %1; cvt.u32.u64 %0, t; }" : "=r"(a) : "l"(p));
    return a;
}
__device__ __forceinline__ float tanh_hw(float x) {
    float y;
    asm("tanh.approx.f32 %0, %1;" : "=f"(y) : "f"(x));
    return y;
}
__device__ __forceinline__ void cp_async16(uint32_t saddr, const void* g) {
    asm volatile("cp.async.cg.shared.global [%0], [%1], 16;\n" :: "r"(saddr), "l"(g));
}
__device__ __forceinline__ void cp_commit() { asm volatile("cp.async.commit_group;\n"); }
__device__ __forceinline__ void cp_wait0()  { asm volatile("cp.async.wait_group 0;\n"); }

__device__ __forceinline__ void lds128(uint32_t* r, uint32_t a) {
    asm volatile("ld.shared.v4.b32 {%0,%1,%2,%3}, [%4];"
        : "=r"(r[0]), "=r"(r[1]), "=r"(r[2]), "=r"(r[3]) : "r"(a));
}
__device__ __forceinline__ void sts32(uint32_t a, uint32_t v) {
    asm volatile("st.shared.b32 [%0], %1;" :: "r"(a), "r"(v) : "memory");
}
__device__ __forceinline__ void red_add(float* p, float v) {
    asm volatile("red.global.add.f32 [%0], %1;" :: "l"(p), "f"(v) : "memory");
}
__device__ __forceinline__ void mma_f16(float c[4], const uint32_t a[4], const uint32_t b[2]) {
    asm volatile(
        "mma.sync.aligned.m16n8k16.row.col.f32.f16.f16.f32 "
        "{%0,%1,%2,%3}, {%4,%5,%6,%7}, {%8,%9}, {%0,%1,%2,%3};\n"
        : "+f"(c[0]), "+f"(c[1]), "+f"(c[2]), "+f"(c[3])
        : "r"(a[0]), "r"(a[1]), "r"(a[2]), "r"(a[3]), "r"(b[0]), "r"(b[1]));
}
__device__ __forceinline__ uint32_t h2bits(float x, float y) {
    __half2 h = __floats2half2_rn(x, y);
    return *reinterpret_cast<uint32_t*>(&h);
}

// ---------------------------------------------------------------------------
// Kernel P: weight pack (coef-folded fp16 fragment order) + zero out0/out1.
// ---------------------------------------------------------------------------
__global__ __launch_bounds__(PREP_THREADS)
void prep_kernel(const float* __restrict__ wpf0, const float* __restrict__ wpi0,
                 const float* __restrict__ wpb0, const float* __restrict__ wpf1,
                 const float* __restrict__ wpi1, const float* __restrict__ wpb1,
                 const float* __restrict__ wpf2, const float* __restrict__ wip0,
                 const float* __restrict__ wip1, float* __restrict__ out) {
    int bid = blockIdx.x;
    if (bid < PREP_W_BLOCKS) {
        const float* Ws[9] = {wpf0, wpi0, wpb0, wpf1, wpi1, wpb1, wpf2, wip0, wip1};
        const float  Cs[9] = {C_B, C_A, C_A, C_B, C_A, C_A, C_B, C_D, C_D};
        int task = bid * PREP_THREADS + threadIdx.x;  // < 73728
        int w    = task >> 13;
        int r    = task & 8191;
        int n    = r >> 5;
        int j    = r & 31;
        int k0   = j * 8;

        float cf = Cs[w];
        const float* src = Ws[w] + n * HDIM + k0;
        float4 v01 = *(const float4*)(src);
        float4 v23 = *(const float4*)(src + 4);
        uint32_t g0 = h2bits(cf * v01.x, cf * v01.y);
        uint32_t g1 = h2bits(cf * v01.z, cf * v01.w);
        uint32_t g2 = h2bits(cf * v23.x, cf * v23.y);
        uint32_t g3 = h2bits(cf * v23.z, cf * v23.w);

        int chunk = k0 >> 5;
        int ck    = k0 & 31;
        int kstep = ck >> 4;
        int khi   = ((ck & 15) >= 8) ? 1 : 0;
        int ng    = n >> 6;
        int nn    = n & 63;
        int i     = (nn >> 3) * 2 + khi;
        int lane0 = (nn & 7) * 4;
        uint32_t base = (uint32_t)chunk * B_FULL + (uint32_t)(ng * 2 + kstep) * 2560
                      + (uint32_t)i * 4;
        unsigned char* dst = g_wpack[w];
        *(uint32_t*)(dst + base + (uint32_t)(lane0 + 0) * 80) = g0;
        *(uint32_t*)(dst + base + (uint32_t)(lane0 + 1) * 80) = g1;
        *(uint32_t*)(dst + base + (uint32_t)(lane0 + 2) * 80) = g2;
        *(uint32_t*)(dst + base + (uint32_t)(lane0 + 3) * 80) = g3;
    } else {
        // zero out0/out1 region: 2*32768*256 floats = 4,194,304 float4
        int idx = (bid - PREP_W_BLOCKS) * PREP_THREADS + threadIdx.x;
        float4* o4 = (float4*)out;
        #pragma unroll
        for (int j = 0; j < 8; j++)
            o4[idx + j * (PREP_Z_BLOCKS * PREP_THREADS)] =
                make_float4(0.f, 0.f, 0.f, 0.f);
    }
}

// ---------------------------------------------------------------------------
// Kernel 2: persistent fused GEMM. blockIdx -> (group gid 0..17, sub 0..15).
// gid = term9*2 + half. Each CTA: load resident B (80KB), loop 16 row-tiles.
// ---------------------------------------------------------------------------
__global__ __launch_bounds__(NTHREADS, 2)
void fused_kernel(const float* __restrict__ data,
                  const float* __restrict__ s0, const float* __restrict__ s1,
                  const float* __restrict__ s2, const float* __restrict__ i0,
                  const float* __restrict__ i1,
                  float* __restrict__ out) {
    extern __shared__ float smem[];
    uint32_t aBase = smem_u32(smem);               // NBUF_A * A_BYTES
    uint32_t bBase = aBase + NBUF_A * A_BYTES;     // B_RES
    float*   nsm   = (float*)((char*)smem + NSM_OFF);   // 128 floats

    int gid   = blockIdx.x >> 4;      // 0..17
    int sub   = blockIdx.x & 15;      // 0..15
    int term9 = gid >> 1;
    int half  = gid & 1;

    // term table: A source, mode, state, alpha, nudge src
    // mode: 0=red-only, 1=red+base(alpha*state), 2=direct, 3=direct+nudge
    const float* Asrc;
    const float* st   = nullptr;
    const float* ndg  = nullptr;
    float alpha = 0.f;
    int   mode;
    int   oid;
    switch (term9) {
    case 0: Asrc = data; mode = 1; st = s0; alpha = ALPHA_S;  oid = 0; break;
    case 1: Asrc = i0;   mode = 0;                            oid = 0; break;
    case 2: Asrc = s1;   mode = 0;                            oid = 0; break;
    case 3: Asrc = s0;   mode = 1; st = s1; alpha = ALPHA_S;  oid = 1; break;
    case 4: Asrc = i1;   mode = 0;                            oid = 1; break;
    case 5: Asrc = s2;   mode = 0;                            oid = 1; break;
    case 6: Asrc = s1;   mode = 2; st = s2; alpha = ALPHA_S2; oid = 2; break;
    case 7: Asrc = s0;   mode = 3; st = i0; alpha = ALPHA_I;  oid = 3; ndg = s1; break;
    default:Asrc = s1;   mode = 3; st = i1; alpha = ALPHA_I;  oid = 4; ndg = s2; break;
    }
    const unsigned char* P = g_wpack[term9];

    int tid   = threadIdx.x;
    int lane  = tid & 31;
    int warp  = tid >> 5;
    int qr    = lane >> 2;
    int qc    = lane & 3;
    int mwarp = warp >> 1;             // 0..3 -> rows mwarp*32
    int ngrp  = warp & 1;              // 0..1 -> 64-col group within half
    int mtb   = mwarp * 2;             // first m16 tile (0..7)

    // ---- resident B: one-time cp.async of this term-half's 80KB ----
    {
        #pragma unroll
        for (int j = 0; j < 20; j++) {
            int tsk = tid + j * NTHREADS;        // < 5120
            int c   = tsk / 640;                 // chunk
            int off = tsk - c * 640;             // 16B unit within chunk-half
            const unsigned char* src = P + (size_t)c * B_FULL
                                     + (size_t)half * B_CHUNK + (size_t)off * 16;
            cp_async16(bBase + (uint32_t)(c * B_CHUNK + off * 16), src);
        }
        cp_commit();
    }

    float acc[2][8][4];
    #pragma unroll
    for (int mt = 0; mt < 2; mt++)
        #pragma unroll
        for (int nt = 0; nt < 8; nt++)
            #pragma unroll
            for (int kx = 0; kx < 4; kx++) acc[mt][nt][kx] = 0.f;

    // ---- A staging: 1024 float4-tasks (128 rows x 8 segs), 4 per thread ----
    int arb = tid >> 3;        // rows arb + 32k, k<4
    int seg = tid & 7;

    auto aoff = [&](int r, int ckg) -> uint32_t {
        int kstep = ckg >> 4;
        int ww    = ckg & 15;
        int tig   = (ww >> 1) & 3;
        int khi   = (ww >= 8) ? 1 : 0;
        int gi    = (khi << 1) | ((r >> 3) & 1);
        int ln    = (r & 7) * 4 + tig;
        return (uint32_t)(((r >> 4) * 2 + kstep) * 512 + ln * 16 + gi * 4);
    };
    uint32_t ao[4][2];
    #pragma unroll
    for (int k = 0; k < 4; k++) {
        ao[k][0] = aoff(arb + 32 * k, seg * 4);
        ao[k][1] = aoff(arb + 32 * k, seg * 4 + 2);
    }

    float4 ra[4];

    auto loadA = [&](int gc) {
        int row0 = (sub * TILES_PER_CTA + (gc >> 3)) * BM;
        int k0   = (gc & 7) * BK;
        #pragma unroll
        for (int k = 0; k < 4; k++)
            ra[k] = *(const float4*)(Asrc + (size_t)(row0 + arb + 32 * k) * HDIM
                                     + k0 + seg * 4);
    };
    auto storeA = [&](int gc) {
        uint32_t base = aBase + (uint32_t)(gc & (NBUF_A - 1)) * A_BYTES;
        #pragma unroll
        for (int k = 0; k < 4; k++) {
            sts32(base + ao[k][0], h2bits(tanh_hw(ra[k].x), tanh_hw(ra[k].y)));
            sts32(base + ao[k][1], h2bits(tanh_hw(ra[k].z), tanh_hw(ra[k].w)));
        }
    };

    auto compute = [&](int gc) {
        uint32_t aB = aBase + (uint32_t)(gc & (NBUF_A - 1)) * A_BYTES;
        uint32_t bB = bBase + (uint32_t)(gc & 7) * B_CHUNK;
        #pragma unroll
        for (int ks = 0; ks < 2; ks++) {
            uint32_t af[2][4], bf[16];
            lds128(af[0], aB + (uint32_t)(((mtb + 0) * 2 + ks) * 512 + lane * 16));
            lds128(af[1], aB + (uint32_t)(((mtb + 1) * 2 + ks) * 512 + lane * 16));
            uint32_t bb = bB + (uint32_t)((ngrp * 2 + ks) * 2560 + lane * 80);
            lds128(bf + 0,  bb);
            lds128(bf + 4,  bb + 16);
            lds128(bf + 8,  bb + 32);
            lds128(bf + 12, bb + 48);
            #pragma unroll
            for (int nt = 0; nt < 8; nt++) {
                mma_f16(acc[0][nt], af[0], bf + nt * 2);
                mma_f16(acc[1][nt], af[1], bf + nt * 2);
            }
        }
    };

    // ---- per-tile epilogue ----
    size_t obase = (size_t)oid * B_ROWS * HDIM;
    int n0 = (half * 2 + ngrp) * 64;
    int m0 = mwarp * 32;

    auto epilogue = [&](int tile) {
        int row0 = (sub * TILES_PER_CTA + tile) * BM;
        if (mode == 3) {
            // in-CTA nudge: 128 row means of tanh(ndg); 8 warps x 16 rows
            int rbase = warp * 16;
            #pragma unroll
            for (int rr = 0; rr < 16; rr++) {
                int row = row0 + rbase + rr;
                const float4* p = (const float4*)(ndg + (size_t)row * HDIM) + lane * 2;
                float4 v = p[0], u = p[1];
                float s = tanh_hw(v.x) + tanh_hw(v.y) + tanh_hw(v.z) + tanh_hw(v.w)
                        + tanh_hw(u.x) + tanh_hw(u.y) + tanh_hw(u.z) + tanh_hw(u.w);
                #pragma unroll
                for (int o = 16; o; o >>= 1) s += __shfl_xor_sync(0xffffffffu, s, o);
                if (lane == 0) nsm[rbase + rr] = s * (C_SOM / (float)HDIM);
            }
            __syncthreads();
        }
        #pragma unroll
        for (int mt = 0; mt < 2; mt++) {
            #pragma unroll
            for (int hq = 0; hq < 2; hq++) {
                int rr  = m0 + mt * 16 + qr + hq * 8;
                int row = row0 + rr;
                float*       op = out + obase + (size_t)row * HDIM + n0;
                if (mode <= 1) {
                    const float* sp = st ? st + (size_t)row * HDIM + n0 : nullptr;
                    #pragma unroll
                    for (int nt = 0; nt < 8; nt++) {
                        int cc = nt * 8 + 2 * qc;
                        float b0 = 0.f, b1 = 0.f;
                        if (mode == 1) {
                            float2 sv = *(const float2*)(sp + cc);
                            b0 = alpha * sv.x; b1 = alpha * sv.y;
                        }
                        red_add(op + cc,     b0 + acc[mt][nt][hq * 2 + 0]);
                        red_add(op + cc + 1, b1 + acc[mt][nt][hq * 2 + 1]);
                    }
                } else {
                    float nv = (mode == 3) ? nsm[rr] : 0.f;
                    const float* sp = st + (size_t)row * HDIM + n0;
                    #pragma unroll
                    for (int nt = 0; nt < 8; nt++) {
                        int cc = nt * 8 + 2 * qc;
                        float2 sv = *(const float2*)(sp + cc);
                        float v0 = alpha * sv.x + acc[mt][nt][hq * 2 + 0] + nv;
                        float v1 = alpha * sv.y + acc[mt][nt][hq * 2 + 1] + nv;
                        *(float2*)(op + cc) = make_float2(v0, v1);
                    }
                }
            }
        }
        // reset accumulators for the next tile
        #pragma unroll
        for (int mt = 0; mt < 2; mt++)
            #pragma unroll
            for (int nt = 0; nt < 8; nt++)
                #pragma unroll
                for (int kx = 0; kx < 4; kx++) acc[mt][nt][kx] = 0.f;
    };

    // ---- prologue ----
    loadA(0);
    storeA(0);
    loadA(1);
    cp_wait0();              // resident B landed
    __syncthreads();         // chunk 0 A + B visible

    // ---- main loop: 128 chunks, epilogue every 8 ----
    for (int gc = 0; gc < GC_TOTAL; gc++) {
        if (gc + 1 < GC_TOTAL) storeA(gc + 1);   // buf (gc+1)%4: free (synced)
        if (gc + 2 < GC_TOTAL) loadA(gc + 2);    // consumed a full compute later
        compute(gc);
        if ((gc & 7) == 7) epilogue(gc >> 3);    // overlaps in-flight loadA
        __syncthreads();
    }
}

// ---------------------------------------------------------------------------
extern "C" void kernel_launch(void* const* d_in, const int* in_sizes, int n_in,
                              void* d_out, int out_size) {
    const float* data = (const float*)d_in[0];
    const float* s0   = (const float*)d_in[1];
    const float* s1   = (const float*)d_in[2];
    const float* s2   = (const float*)d_in[3];
    const float* i0   = (const float*)d_in[4];
    const float* i1   = (const float*)d_in[5];
    const float* wpf0 = (const float*)d_in[6];
    const float* wpf1 = (const float*)d_in[7];
    const float* wpf2 = (const float*)d_in[8];
    const float* wpb0 = (const float*)d_in[9];
    const float* wpb1 = (const float*)d_in[10];
    const float* wip0 = (const float*)d_in[11];
    const float* wip1 = (const float*)d_in[12];
    const float* wpi0 = (const float*)d_in[13];
    const float* wpi1 = (const float*)d_in[14];
    float* out = (float*)d_out;

    cudaFuncSetAttribute(fused_kernel,
                         cudaFuncAttributeMaxDynamicSharedMemorySize, SMEM_BYTES);

    // weight pack + zero out0/out1 (red targets) in one launch
    prep_kernel<<<PREP_W_BLOCKS + PREP_Z_BLOCKS, PREP_THREADS>>>(
        wpf0, wpi0, wpb0, wpf1, wpi1, wpb1, wpf2, wip0, wip1, out);

    // 18 term-half groups x 16 CTAs, one full wave of 296 slots.
    fused_kernel<<<GRID_FUSED, NTHREADS, SMEM_BYTES>>>(data, s0, s1, s2,
                                                       i0, i1, out);
}

// round 17
// speedup vs baseline: 1.8092x; 1.8092x over previous
#include <cuda_runtime.h>
#include <cuda_fp16.h>
#include <cstdint>

// dendriticNet fused stepper, GB300 sm_103a — Round 17.
// R12 (best: 176.9us) with ONE change: the per-chunk 20KB B-fill becomes a
// single cp.async.bulk (TMA bulk copy, async proxy) issued by one thread,
// tracked by per-buffer mbarriers. This removes the 1280 cp.async.cg ops'
// LSU-issue + L1-wavefront cost per chunk (~160 cyc of a ~1250-cyc budget,
// x2 CTAs) from the measured ~90%-utilized L1 port. Everything else (tiling,
// A staging, epilogue, in-CTA nudge, weights-only prep) is R12 verbatim.
//
// Graph-capture safe: kernel launches only, no allocs, scratch = __device__.

#define B_ROWS   32768
#define HDIM     256
#define BM       64
#define BN       256
#define BK       32
#define NTHREADS 256
#define NBUF     4

#define A_BYTES  4096            // 64 x 32 halves, A-fragment order
#define B_BYTES  20480           // 256 x 32 halves, B-fragment order, 80B/lane
#define W_PACK_BYTES (8 * B_BYTES)
// smem: A bufs | B bufs | 4 mbarriers
#define CTRL_OFF  (NBUF * A_BYTES + NBUF * B_BYTES)      // 98304
#define SMEM_BYTES (CTRL_OFF + 64)

// Folded constants (DT=0.1, GLK=0.1, GB=1.0, GA=0.8, GD=1.0, GSOM=0.8)
#define ALPHA_S   0.81f
#define ALPHA_S2  0.89f
#define ALPHA_I   0.81f
#define C_B       0.10f
#define C_A       0.08f
#define C_D       0.10f
#define C_SOM     0.08f

#define PREP_THREADS  512
#define PREP_W_BLOCKS 144

__device__ __align__(16) unsigned char g_wpack[9][W_PACK_BYTES];

// ---------------------------------------------------------------------------
// helpers
// ---------------------------------------------------------------------------
__device__ __forceinline__ uint32_t smem_u32(const void* p) {
    uint32_t a;
    asm("{ .reg .u64 t; cvta.to.shared.u64 t, %1; cvt.u32.u64 %0, t; }" : "=r"(a) : "l"(p));
    return a;
}
__device__ __forceinline__ float tanh_hw(float x) {
    float y;
    asm("tanh.approx.f32 %0, %1;" : "=f"(y) : "f"(x));
    return y;
}
__device__ __forceinline__ void lds128(uint32_t* r, uint32_t a) {
    asm volatile("ld.shared.v4.b32 {%0,%1,%2,%3}, [%4];"
        : "=r"(r[0]), "=r"(r[1]), "=r"(r[2]), "=r"(r[3]) : "r"(a));
}
__device__ __forceinline__ void sts32(uint32_t a, uint32_t v) {
    asm volatile("st.shared.b32 [%0], %1;" :: "r"(a), "r"(v) : "memory");
}
__device__ __forceinline__ void mma_f16(float c[4], const uint32_t a[4], const uint32_t b[2]) {
    asm volatile(
        "mma.sync.aligned.m16n8k16.row.col.f32.f16.f16.f32 "
        "{%0,%1,%2,%3}, {%4,%5,%6,%7}, {%8,%9}, {%0,%1,%2,%3};\n"
        : "+f"(c[0]), "+f"(c[1]), "+f"(c[2]), "+f"(c[3])
        : "r"(a[0]), "r"(a[1]), "r"(a[2]), "r"(a[3]), "r"(b[0]), "r"(b[1]));
}
__device__ __forceinline__ uint32_t h2bits(float x, float y) {
    __half2 h = __floats2half2_rn(x, y);
    return *reinterpret_cast<uint32_t*>(&h);
}

// ---- mbarrier + bulk copy ----
#define MBAR_INIT(mb, n) \
    asm volatile("mbarrier.init.shared.b64 [%0], %1;" :: "r"(mb), "r"((uint32_t)(n)) : "memory")
#define MBAR_EXPECT_TX(mb, bytes) \
    asm volatile("mbarrier.arrive.expect_tx.shared.b64 _, [%0], %1;" \
                 :: "r"(mb), "r"((uint32_t)(bytes)) : "memory")
__device__ __forceinline__ void bulk_g2s(uint32_t dst, const void* src,
                                         uint32_t bytes, uint32_t mbar) {
    asm volatile(
        "cp.async.bulk.shared::cluster.global.mbarrier::complete_tx::bytes "
        "[%0], [%1], %2, [%3];"
        :: "r"(dst), "l"(src), "r"(bytes), "r"(mbar) : "memory");
}
__device__ __forceinline__ void mbar_wait(uint32_t mb, uint32_t parity) {
    uint32_t done;
    asm volatile(
        "{\n\t.reg .pred p;\n\t"
        "mbarrier.try_wait.parity.acquire.cta.shared::cta.b64 p, [%1], %2;\n\t"
        "selp.b32 %0, 1, 0, p;\n\t}"
        : "=r"(done) : "r"(mb), "r"(parity) : "memory");
    if (!done) {
        asm volatile(
            "{\n\t.reg .pred P1;\n\t"
            "W_%=:\n\t"
            "mbarrier.try_wait.parity.acquire.cta.shared::cta.b64 P1, [%0], %1, 0x989680;\n\t"
            "@P1 bra.uni D_%=;\n\t"
            "bra.uni W_%=;\n\t"
            "D_%=:\n\t}"
            :: "r"(mb), "r"(parity) : "memory");
    }
}

// ---------------------------------------------------------------------------
// Kernel P: weights -> coef*fp16, B-fragment order (weights only).
// ---------------------------------------------------------------------------
__global__ __launch_bounds__(PREP_THREADS)
void prep_kernel(const float* __restrict__ wpf0, const float* __restrict__ wpi0,
                 const float* __restrict__ wpb0, const float* __restrict__ wpf1,
                 const float* __restrict__ wpi1, const float* __restrict__ wpb1,
                 const float* __restrict__ wpf2, const float* __restrict__ wip0,
                 const float* __restrict__ wip1) {
    const float* Ws[9] = {wpf0, wpi0, wpb0, wpf1, wpi1, wpb1, wpf2, wip0, wip1};
    const float  Cs[9] = {C_B, C_A, C_A, C_B, C_A, C_A, C_B, C_D, C_D};
    int task = blockIdx.x * PREP_THREADS + threadIdx.x;  // < 73728
    int w    = task >> 13;
    int r    = task & 8191;
    int n    = r >> 5;
    int j    = r & 31;
    int k0   = j * 8;

    float cf = Cs[w];
    const float* src = Ws[w] + n * HDIM + k0;
    float4 v01 = *(const float4*)(src);
    float4 v23 = *(const float4*)(src + 4);
    uint32_t g0 = h2bits(cf * v01.x, cf * v01.y);
    uint32_t g1 = h2bits(cf * v01.z, cf * v01.w);
    uint32_t g2 = h2bits(cf * v23.x, cf * v23.y);
    uint32_t g3 = h2bits(cf * v23.z, cf * v23.w);

    int chunk = k0 >> 5;
    int ck    = k0 & 31;
    int kstep = ck >> 4;
    int khi   = ((ck & 15) >= 8) ? 1 : 0;
    int ng    = n >> 6;
    int nn    = n & 63;
    int i     = (nn >> 3) * 2 + khi;
    int lane0 = (nn & 7) * 4;
    uint32_t base = (uint32_t)chunk * B_BYTES + (uint32_t)(ng * 2 + kstep) * 2560
                  + (uint32_t)i * 4;
    unsigned char* dst = g_wpack[w];
    *(uint32_t*)(dst + base + (uint32_t)(lane0 + 0) * 80) = g0;
    *(uint32_t*)(dst + base + (uint32_t)(lane0 + 1) * 80) = g1;
    *(uint32_t*)(dst + base + (uint32_t)(lane0 + 2) * 80) = g2;
    *(uint32_t*)(dst + base + (uint32_t)(lane0 + 3) * 80) = g3;
}

// ---------------------------------------------------------------------------
// Kernel 2: fused fp16 GEMM + epilogue. 256 threads, 8 warps 2(M)x4(N),
// warp tile 32x64, CTA tile 64x256, 2 CTAs/SM. B-fill = cp.async.bulk.
// ---------------------------------------------------------------------------
__global__ __launch_bounds__(NTHREADS, 2)
void fused_kernel(const float* __restrict__ data,
                  const float* __restrict__ s0, const float* __restrict__ s1,
                  const float* __restrict__ s2, const float* __restrict__ i0,
                  const float* __restrict__ i1,
                  float* __restrict__ out) {
    extern __shared__ float smem[];
    uint32_t aBase = smem_u32(smem);                 // NBUF * A_BYTES
    uint32_t bBase = aBase + NBUF * A_BYTES;         // NBUF * B_BYTES
    uint32_t ctrl  = aBase + CTRL_OFF;               // 4 mbarriers (8B each)

    int bid    = blockIdx.x;
    int out_id = bid % 5;
    int row0   = (bid / 5) * BM;

    const float *A0, *A1 = nullptr, *A2 = nullptr;
    const unsigned char *P0, *P1 = nullptr, *P2 = nullptr;
    int   nterms;
    float alpha;
    const float* ndgsrc = nullptr;    // in-CTA nudge source (s1 or s2)
    const float* st;

    switch (out_id) {
    case 0: nterms = 3; alpha = ALPHA_S;  st = s0;
            A0 = data; P0 = g_wpack[0];
            A1 = i0;   P1 = g_wpack[1];
            A2 = s1;   P2 = g_wpack[2];  break;
    case 1: nterms = 3; alpha = ALPHA_S;  st = s1;
            A0 = s0;   P0 = g_wpack[3];
            A1 = i1;   P1 = g_wpack[4];
            A2 = s2;   P2 = g_wpack[5];  break;
    case 2: nterms = 1; alpha = ALPHA_S2; st = s2;
            A0 = s1;   P0 = g_wpack[6];  break;
    case 3: nterms = 1; alpha = ALPHA_I;  st = i0; ndgsrc = s1;
            A0 = s0;   P0 = g_wpack[7];  break;
    default:nterms = 1; alpha = ALPHA_I;  st = i1; ndgsrc = s2;
            A0 = s1;   P0 = g_wpack[8];  break;
    }
    const int NCH = nterms * (HDIM / BK);   // 8 or 24

    int tid  = threadIdx.x;
    int lane = tid & 31;
    int warp = tid >> 5;
    int qr   = lane >> 2;
    int qc   = lane & 3;
    int mtb  = (warp >> 2) * 2;        // A m16-tile base (0 or 2)
    int ngrp = warp & 3;               // B n-group (64 cols)

    // mbarrier init (count=1: thread0's expect_tx arrive)
    if (tid == 0) {
        #pragma unroll
        for (int s = 0; s < NBUF; s++) MBAR_INIT(ctrl + 8 * s, 1);
    }
    __syncthreads();

    float acc[2][8][4];
    #pragma unroll
    for (int mt = 0; mt < 2; mt++)
        #pragma unroll
        for (int nt = 0; nt < 8; nt++)
            #pragma unroll
            for (int kx = 0; kx < 4; kx++) acc[mt][nt][kx] = 0.f;

    // ---- A staging: 512 float4-tasks (64 rows x 8 segs), 2 per thread ----
    int ar0 = tid >> 3;        // rows 0..31
    int seg = tid & 7;         // float4 index within 32-float row-chunk
    int ar1 = ar0 + 32;        // rows 32..63

    auto aoff = [&](int r, int ckg) -> uint32_t {
        int kstep = ckg >> 4;
        int ww    = ckg & 15;
        int tig   = (ww >> 1) & 3;
        int khi   = (ww >= 8) ? 1 : 0;
        int gi    = (khi << 1) | ((r >> 3) & 1);
        int ln    = (r & 7) * 4 + tig;
        return (uint32_t)(((r >> 4) * 2 + kstep) * 512 + ln * 16 + gi * 4);
    };
    uint32_t ao00 = aoff(ar0, seg * 4);
    uint32_t ao01 = aoff(ar0, seg * 4 + 2);
    uint32_t ao10 = aoff(ar1, seg * 4);
    uint32_t ao11 = aoff(ar1, seg * 4 + 2);

    float4 ra0, ra1;

    auto loadA = [&](int c) {
        int t  = c >> 3;
        int k0 = (c & 7) * BK;
        const float* A = (t == 0) ? A0 : ((t == 1) ? A1 : A2);
        ra0 = *(const float4*)(A + (size_t)(row0 + ar0) * HDIM + k0 + seg * 4);
        ra1 = *(const float4*)(A + (size_t)(row0 + ar1) * HDIM + k0 + seg * 4);
    };
    auto storeA = [&](int c) {
        uint32_t base = aBase + (uint32_t)(c & (NBUF - 1)) * A_BYTES;
        sts32(base + ao00, h2bits(tanh_hw(ra0.x), tanh_hw(ra0.y)));
        sts32(base + ao01, h2bits(tanh_hw(ra0.z), tanh_hw(ra0.w)));
        sts32(base + ao10, h2bits(tanh_hw(ra1.x), tanh_hw(ra1.y)));
        sts32(base + ao11, h2bits(tanh_hw(ra1.z), tanh_hw(ra1.w)));
    };

    // ---- B staging: one bulk copy per chunk, issued by thread 0 ----
    auto loadB = [&](int c) {           // call from tid==0 only
        int t = c >> 3;
        const unsigned char* src =
            ((t == 0) ? P0 : ((t == 1) ? P1 : P2)) + (size_t)(c & 7) * B_BYTES;
        int buf = c & (NBUF - 1);
        uint32_t mb = ctrl + 8 * buf;
        MBAR_EXPECT_TX(mb, B_BYTES);
        bulk_g2s(bBase + (uint32_t)buf * B_BYTES, src, B_BYTES, mb);
    };

    auto compute = [&](int c) {
        uint32_t aB = aBase + (uint32_t)(c & (NBUF - 1)) * A_BYTES;
        uint32_t bB = bBase + (uint32_t)(c & (NBUF - 1)) * B_BYTES;
        #pragma unroll
        for (int ks = 0; ks < 2; ks++) {
            uint32_t af[2][4], bf[16];
            lds128(af[0], aB + (uint32_t)(((mtb + 0) * 2 + ks) * 512 + lane * 16));
            lds128(af[1], aB + (uint32_t)(((mtb + 1) * 2 + ks) * 512 + lane * 16));
            uint32_t bb = bB + (uint32_t)((ngrp * 2 + ks) * 2560 + lane * 80);
            lds128(bf + 0,  bb);
            lds128(bf + 4,  bb + 16);
            lds128(bf + 8,  bb + 32);
            lds128(bf + 12, bb + 48);
            #pragma unroll
            for (int nt = 0; nt < 8; nt++) {
                mma_f16(acc[0][nt], af[0], bf + nt * 2);
                mma_f16(acc[1][nt], af[1], bf + nt * 2);
            }
        }
    };

    // ---- pipeline: same adjacency as R12; B via bulk + mbarrier ----
    if (tid == 0) { loadB(0); loadB(1); loadB(2); }
    loadA(0);
    storeA(0);
    loadA(1);
    mbar_wait(ctrl + 0, 0);   // B chunk 0 done
    __syncthreads();          // chunk 0 (A store + B wait) visible to all

    for (int c = 0; c < NCH; c++) {
        if (c + 1 < NCH) storeA(c + 1);     // buf (c+1)%4: compute(c-3) done+synced
        if (c + 2 < NCH) loadA(c + 2);      // full compute of cover before its store
        if (c + 3 < NCH && tid == 0) loadB(c + 3);  // buf (c-1)%4: done+synced
        compute(c);
        if (c + 1 < NCH)                    // B chunk c+1 done (issued at c-2)
            mbar_wait(ctrl + 8 * ((c + 1) & (NBUF - 1)), ((c + 1) >> 2) & 1);
        __syncthreads();                    // chunk c+1 visible
    }

    // ---- in-CTA nudge (out3/out4): 64 row means of tanh(src) ----
    float* nsm = smem;                      // data buffers dead after final barrier
    if (ndgsrc) {
        int rbase = warp * 8;
        #pragma unroll
        for (int rr = 0; rr < 8; rr++) {
            int row = row0 + rbase + rr;
            const float4* p = (const float4*)(ndgsrc + (size_t)row * HDIM) + lane * 2;
            float4 v = p[0], u = p[1];
            float s = tanh_hw(v.x) + tanh_hw(v.y) + tanh_hw(v.z) + tanh_hw(v.w)
                    + tanh_hw(u.x) + tanh_hw(u.y) + tanh_hw(u.z) + tanh_hw(u.w);
            #pragma unroll
            for (int o = 16; o; o >>= 1) s += __shfl_xor_sync(0xffffffffu, s, o);
            if (lane == 0) nsm[rbase + rr] = s * (C_SOM / (float)HDIM);
        }
        __syncthreads();
    }

    // ---- epilogue: out = alpha*state + acc (+ nudge for i-outputs) ----
    size_t obase = (size_t)out_id * B_ROWS * HDIM;
    int m0 = (warp >> 2) * 32;
    int n0 = ngrp * 64;
    #pragma unroll
    for (int mt = 0; mt < 2; mt++) {
        #pragma unroll
        for (int half = 0; half < 2; half++) {
            int rr  = m0 + mt * 16 + qr + half * 8;
            int row = row0 + rr;
            float nv = ndgsrc ? nsm[rr] : 0.f;
            const float* sp = st + (size_t)row * HDIM + n0;
            float*       op = out + obase + (size_t)row * HDIM + n0;
            #pragma unroll
            for (int nt = 0; nt < 8; nt++) {
                int cc = nt * 8 + 2 * qc;
                float2 sv = *(const float2*)(sp + cc);
                float v0 = alpha * sv.x + acc[mt][nt][half * 2 + 0] + nv;
                float v1 = alpha * sv.y + acc[mt][nt][half * 2 + 1] + nv;
                *(float2*)(op + cc) = make_float2(v0, v1);
            }
        }
    }
}

// ---------------------------------------------------------------------------
extern "C" void kernel_launch(void* const* d_in, const int* in_sizes, int n_in,
                              void* d_out, int out_size) {
    const float* data = (const float*)d_in[0];
    const float* s0   = (const float*)d_in[1];
    const float* s1   = (const float*)d_in[2];
    const float* s2   = (const float*)d_in[3];
    const float* i0   = (const float*)d_in[4];
    const float* i1   = (const float*)d_in[5];
    const float* wpf0 = (const float*)d_in[6];
    const float* wpf1 = (const float*)d_in[7];
    const float* wpf2 = (const float*)d_in[8];
    const float* wpb0 = (const float*)d_in[9];
    const float* wpb1 = (const float*)d_in[10];
    const float* wip0 = (const float*)d_in[11];
    const float* wip1 = (const float*)d_in[12];
    const float* wpi0 = (const float*)d_in[13];
    const float* wpi1 = (const float*)d_in[14];
    float* out = (float*)d_out;

    cudaFuncSetAttribute(fused_kernel,
                         cudaFuncAttributeMaxDynamicSharedMemorySize, SMEM_BYTES);

    // weights-only prep (coef folded into fp16 pack, fragment order)
    prep_kernel<<<PREP_W_BLOCKS, PREP_THREADS>>>(
        wpf0, wpi0, wpb0, wpf1, wpi1, wpb1, wpf2, wip0, wip1);

    // 5 outputs x 512 row tiles = 2560 CTAs; adjacent bids = different outputs
    // on the same rows -> L2 reuse of activations.
    fused_kernel<<<2560, NTHREADS, SMEM_BYTES>>>(data, s0, s1, s2, i0, i1, out);
}